// round 7
// baseline (speedup 1.0000x reference)
#include <cuda_runtime.h>

// Problem constants (fixed by the reference)
#define N_NODES 50000
#define N_EDGES 1250000
#define D 64
#define D4 16                 // float4 per feature row
#define L 3
#define OUT_C4 64             // 256 output cols / 4

// Scratch (allocation-free rule: __device__ global)
__device__ float g_agg[N_NODES * D];

// ---------------------------------------------------------------------------
// init: out[:, 0:64) = h  AND  agg = 0   (fused)
// ---------------------------------------------------------------------------
__global__ void init_kernel(const float4* __restrict__ h4,
                            float4* __restrict__ out4,
                            float4* __restrict__ agg4) {
    int idx = blockIdx.x * blockDim.x + threadIdx.x;
    if (idx >= N_NODES * D4) return;
    int row = idx >> 4;
    int c   = idx & 15;
    out4[row * OUT_C4 + c] = h4[idx];
    agg4[idx] = make_float4(0.f, 0.f, 0.f, 0.f);
}

// ---------------------------------------------------------------------------
// Edge-parallel gather-scale-scatter. Features are read from the out buffer
// (column slice of width 64 at col_off4), agg[dst] += feat[src] * w.
// One thread per (edge, float4-chunk); 16 chunks per edge.
// ---------------------------------------------------------------------------
__global__ void scatter_kernel(const float4* __restrict__ out4,
                               int col_off4,
                               const float*  __restrict__ ew,
                               const int*    __restrict__ src,
                               const int*    __restrict__ dst,
                               float4*       __restrict__ agg4) {
    int idx = blockIdx.x * blockDim.x + threadIdx.x;
    if (idx >= N_EDGES * D4) return;
    int e = idx >> 4;
    int c = idx & 15;

    int   s = src[e];
    int   d = dst[e];
    float w = ew[e];

    float4 v = out4[s * OUT_C4 + col_off4 + c];
    v.x *= w; v.y *= w; v.z *= w; v.w *= w;

#if defined(__CUDA_ARCH__) && (__CUDA_ARCH__ >= 900)
    atomicAdd(&agg4[d * D4 + c], v);   // RED.E.ADD.128
#else
    float* p = (float*)&agg4[d * D4 + c];
    atomicAdd(p + 0, v.x); atomicAdd(p + 1, v.y);
    atomicAdd(p + 2, v.z); atomicAdd(p + 3, v.w);
#endif
}

// ---------------------------------------------------------------------------
// Register-blocked transform:  y = agg @ W + b  (optional tanh)
//   - Block = 128 threads = 32 strips x 4 col-groups; strip owns 3 rows.
//   - Block covers 96 rows.  Thread computes a 3-row x 16-col register tile.
//   - W held in smem in a bank-permuted float4 layout (conflict-free reads).
//   - agg rows held in smem with stride-65 padding (conflict-free scalar reads).
//   - After loading agg into smem, agg is zeroed (ready for next scatter).
// Writes result into out[:, col_off4*4 : +64).
// ---------------------------------------------------------------------------
#define TRB 96   // rows per block

template <bool TANH_AND_ZERO>
__global__ void __launch_bounds__(128) transform_kernel(
        float4* __restrict__ agg4,
        const float4* __restrict__ W4,   // [1024] float4 = [64,64] row-major
        const float*  __restrict__ b,    // [64]
        float4* __restrict__ out4,       // [N, 64] float4
        int col_off4) {
    __shared__ float4 sW[1024];          // 16 KB, permuted: sW[(cq*64+k)*4+cg]
    __shared__ float  sA[TRB * 65];      // ~25 KB, padded rows
    __shared__ float  sb[D];

    int tid = threadIdx.x;

    // Load W into permuted smem layout.
    // Global chunk i = k*16 + (cg*4 + cq)  ->  sW[(cq*64 + k)*4 + cg]
    for (int i = tid; i < 1024; i += 128) {
        int k  = i >> 4;
        int ch = i & 15;
        int cg = ch >> 2;
        int cq = ch & 3;
        sW[(cq * 64 + k) * 4 + cg] = W4[i];
    }
    if (tid < D) sb[tid] = b[tid];

    // Load agg rows into smem (padded) and zero agg in gmem.
    int row0  = blockIdx.x * TRB;
    int base4 = row0 * D4;
    const float4 z4 = make_float4(0.f, 0.f, 0.f, 0.f);
    for (int i = tid; i < TRB * D4; i += 128) {
        float4 v = z4;
        int g = base4 + i;
        if (g < N_NODES * D4) {
            v = agg4[g];
            if (TANH_AND_ZERO) agg4[g] = z4;
        }
        int lr = i >> 4;
        int c4 = i & 15;
        float* p = &sA[lr * 65 + c4 * 4];
        p[0] = v.x; p[1] = v.y; p[2] = v.z; p[3] = v.w;
    }
    __syncthreads();

    int cg    = tid & 3;        // col group: cols [cg*16, cg*16+16)
    int strip = tid >> 2;       // 0..31
    int lr0   = strip * 3;      // 3 rows per strip; strips 0..31 -> rows 0..95

    // Init accumulators with bias
    float4 acc[3][4];
    #pragma unroll
    for (int r = 0; r < 3; r++)
        #pragma unroll
        for (int cq = 0; cq < 4; cq++) {
            int c = cg * 16 + cq * 4;
            acc[r][cq] = make_float4(sb[c], sb[c + 1], sb[c + 2], sb[c + 3]);
        }

    // Main loop over k
    #pragma unroll 4
    for (int k = 0; k < D; k++) {
        float a0 = sA[(lr0 + 0) * 65 + k];
        float a1 = sA[(lr0 + 1) * 65 + k];
        float a2 = sA[(lr0 + 2) * 65 + k];
        float4 w[4];
        #pragma unroll
        for (int cq = 0; cq < 4; cq++)
            w[cq] = sW[(cq * 64 + k) * 4 + cg];

        #pragma unroll
        for (int cq = 0; cq < 4; cq++) {
            acc[0][cq].x = fmaf(a0, w[cq].x, acc[0][cq].x);
            acc[0][cq].y = fmaf(a0, w[cq].y, acc[0][cq].y);
            acc[0][cq].z = fmaf(a0, w[cq].z, acc[0][cq].z);
            acc[0][cq].w = fmaf(a0, w[cq].w, acc[0][cq].w);
            acc[1][cq].x = fmaf(a1, w[cq].x, acc[1][cq].x);
            acc[1][cq].y = fmaf(a1, w[cq].y, acc[1][cq].y);
            acc[1][cq].z = fmaf(a1, w[cq].z, acc[1][cq].z);
            acc[1][cq].w = fmaf(a1, w[cq].w, acc[1][cq].w);
            acc[2][cq].x = fmaf(a2, w[cq].x, acc[2][cq].x);
            acc[2][cq].y = fmaf(a2, w[cq].y, acc[2][cq].y);
            acc[2][cq].z = fmaf(a2, w[cq].z, acc[2][cq].z);
            acc[2][cq].w = fmaf(a2, w[cq].w, acc[2][cq].w);
        }
    }

    // Epilogue: optional tanh, store to out column slice
    #pragma unroll
    for (int r = 0; r < 3; r++) {
        int row = row0 + lr0 + r;
        if (row >= N_NODES) continue;
        #pragma unroll
        for (int cq = 0; cq < 4; cq++) {
            float4 v = acc[r][cq];
            if (TANH_AND_ZERO) {
                v.x = tanhf(v.x); v.y = tanhf(v.y);
                v.z = tanhf(v.z); v.w = tanhf(v.w);
            }
            out4[row * OUT_C4 + col_off4 + cg * 4 + cq] = v;
        }
    }
}

// ---------------------------------------------------------------------------
// Launch
// ---------------------------------------------------------------------------
extern "C" void kernel_launch(void* const* d_in, const int* in_sizes, int n_in,
                              void* d_out, int out_size) {
    const float* h   = (const float*)d_in[0];  // [50000, 64]
    const float* ew  = (const float*)d_in[1];  // [1250000]
    const float* Ws  = (const float*)d_in[2];  // [3, 64, 64]
    const float* bs  = (const float*)d_in[3];  // [3, 64]
    const int*   src = (const int*)d_in[4];    // [1250000]
    const int*   dst = (const int*)d_in[5];    // [1250000]
    float*       out = (float*)d_out;          // [50000, 256]

    float* gagg;
    cudaGetSymbolAddress((void**)&gagg, g_agg);

    const int THREADS = 256;

    // init: copy h into out[:,0:64) + zero agg
    {
        int total = N_NODES * D4;
        init_kernel<<<(total + THREADS - 1) / THREADS, THREADS>>>(
            (const float4*)h, (float4*)out, (float4*)gagg);
    }

    int scat_total   = N_EDGES * D4;
    int scat_blocks  = (scat_total + THREADS - 1) / THREADS;
    int xform_blocks = (N_NODES + TRB - 1) / TRB;   // 521

    for (int layer = 0; layer < L; layer++) {
        const float* W = Ws + layer * D * D;
        const float* b = bs + layer * D;
        int in_off4    = layer * D4;        // read slice
        int out_off4   = (layer + 1) * D4;  // write slice

        scatter_kernel<<<scat_blocks, THREADS>>>(
            (const float4*)out, in_off4, ew, src, dst, (float4*)gagg);

        if (layer < L - 1) {
            transform_kernel<true><<<xform_blocks, 128>>>(
                (float4*)gagg, (const float4*)W, b, (float4*)out, out_off4);
        } else {
            transform_kernel<false><<<xform_blocks, 128>>>(
                (float4*)gagg, (const float4*)W, b, (float4*)out, out_off4);
        }
    }
}

// round 8
// speedup vs baseline: 1.0009x; 1.0009x over previous
#include <cuda_runtime.h>

// Problem constants (fixed by the reference)
#define N_NODES 50000
#define N_EDGES 1250000
#define D 64
#define D4 16                 // float4 per feature row
#define L 3
#define OUT_C4 64             // 256 output cols / 4

// Scratch (allocation-free rule: __device__ global)
__device__ float g_agg[N_NODES * D];

// ---------------------------------------------------------------------------
// init: out[:, 0:64) = h  AND  agg = 0   (fused)
// ---------------------------------------------------------------------------
__global__ void init_kernel(const float4* __restrict__ h4,
                            float4* __restrict__ out4,
                            float4* __restrict__ agg4) {
    int idx = blockIdx.x * blockDim.x + threadIdx.x;
    if (idx >= N_NODES * D4) return;
    int row = idx >> 4;
    int c   = idx & 15;
    out4[row * OUT_C4 + c] = h4[idx];
    agg4[idx] = make_float4(0.f, 0.f, 0.f, 0.f);
}

// ---------------------------------------------------------------------------
// Edge-parallel gather-scale-scatter. Features are read from the out buffer
// (column slice of width 64 at col_off4), agg[dst] += feat[src] * w.
// One thread per (edge, float4-chunk); 16 chunks per edge.
// ---------------------------------------------------------------------------
__global__ void scatter_kernel(const float4* __restrict__ out4,
                               int col_off4,
                               const float*  __restrict__ ew,
                               const int*    __restrict__ src,
                               const int*    __restrict__ dst,
                               float4*       __restrict__ agg4) {
    int idx = blockIdx.x * blockDim.x + threadIdx.x;
    if (idx >= N_EDGES * D4) return;
    int e = idx >> 4;
    int c = idx & 15;

    int   s = src[e];
    int   d = dst[e];
    float w = ew[e];

    float4 v = out4[s * OUT_C4 + col_off4 + c];
    v.x *= w; v.y *= w; v.z *= w; v.w *= w;

#if defined(__CUDA_ARCH__) && (__CUDA_ARCH__ >= 900)
    atomicAdd(&agg4[d * D4 + c], v);   // RED.E.ADD.128
#else
    float* p = (float*)&agg4[d * D4 + c];
    atomicAdd(p + 0, v.x); atomicAdd(p + 1, v.y);
    atomicAdd(p + 2, v.z); atomicAdd(p + 3, v.w);
#endif
}

// ---------------------------------------------------------------------------
// Register-blocked transform:  y = agg @ W + b  (optional tanh)
//   - Block = 128 threads = 32 strips x 4 col-groups; strip owns 3 rows.
//   - Block covers 96 rows.  Thread computes a 3-row x 16-col register tile.
//   - W held in smem in a bank-permuted float4 layout (conflict-free reads).
//   - agg rows held in smem with stride-65 padding (conflict-free scalar reads).
//   - After loading agg into smem, agg is zeroed (ready for next scatter).
// Writes result into out[:, col_off4*4 : +64).
// ---------------------------------------------------------------------------
#define TRB 96   // rows per block

template <bool TANH_AND_ZERO>
__global__ void __launch_bounds__(128) transform_kernel(
        float4* __restrict__ agg4,
        const float4* __restrict__ W4,   // [1024] float4 = [64,64] row-major
        const float*  __restrict__ b,    // [64]
        float4* __restrict__ out4,       // [N, 64] float4
        int col_off4) {
    __shared__ float4 sW[1024];          // 16 KB, permuted: sW[(cq*64+k)*4+cg]
    __shared__ float  sA[TRB * 65];      // ~25 KB, padded rows
    __shared__ float  sb[D];

    int tid = threadIdx.x;

    // Load W into permuted smem layout.
    // Global chunk i = k*16 + (cg*4 + cq)  ->  sW[(cq*64 + k)*4 + cg]
    for (int i = tid; i < 1024; i += 128) {
        int k  = i >> 4;
        int ch = i & 15;
        int cg = ch >> 2;
        int cq = ch & 3;
        sW[(cq * 64 + k) * 4 + cg] = W4[i];
    }
    if (tid < D) sb[tid] = b[tid];

    // Load agg rows into smem (padded) and zero agg in gmem.
    int row0  = blockIdx.x * TRB;
    int base4 = row0 * D4;
    const float4 z4 = make_float4(0.f, 0.f, 0.f, 0.f);
    for (int i = tid; i < TRB * D4; i += 128) {
        float4 v = z4;
        int g = base4 + i;
        if (g < N_NODES * D4) {
            v = agg4[g];
            if (TANH_AND_ZERO) agg4[g] = z4;
        }
        int lr = i >> 4;
        int c4 = i & 15;
        float* p = &sA[lr * 65 + c4 * 4];
        p[0] = v.x; p[1] = v.y; p[2] = v.z; p[3] = v.w;
    }
    __syncthreads();

    int cg    = tid & 3;        // col group: cols [cg*16, cg*16+16)
    int strip = tid >> 2;       // 0..31
    int lr0   = strip * 3;      // 3 rows per strip; strips 0..31 -> rows 0..95

    // Init accumulators with bias
    float4 acc[3][4];
    #pragma unroll
    for (int r = 0; r < 3; r++)
        #pragma unroll
        for (int cq = 0; cq < 4; cq++) {
            int c = cg * 16 + cq * 4;
            acc[r][cq] = make_float4(sb[c], sb[c + 1], sb[c + 2], sb[c + 3]);
        }

    // Main loop over k
    #pragma unroll 4
    for (int k = 0; k < D; k++) {
        float a0 = sA[(lr0 + 0) * 65 + k];
        float a1 = sA[(lr0 + 1) * 65 + k];
        float a2 = sA[(lr0 + 2) * 65 + k];
        float4 w[4];
        #pragma unroll
        for (int cq = 0; cq < 4; cq++)
            w[cq] = sW[(cq * 64 + k) * 4 + cg];

        #pragma unroll
        for (int cq = 0; cq < 4; cq++) {
            acc[0][cq].x = fmaf(a0, w[cq].x, acc[0][cq].x);
            acc[0][cq].y = fmaf(a0, w[cq].y, acc[0][cq].y);
            acc[0][cq].z = fmaf(a0, w[cq].z, acc[0][cq].z);
            acc[0][cq].w = fmaf(a0, w[cq].w, acc[0][cq].w);
            acc[1][cq].x = fmaf(a1, w[cq].x, acc[1][cq].x);
            acc[1][cq].y = fmaf(a1, w[cq].y, acc[1][cq].y);
            acc[1][cq].z = fmaf(a1, w[cq].z, acc[1][cq].z);
            acc[1][cq].w = fmaf(a1, w[cq].w, acc[1][cq].w);
            acc[2][cq].x = fmaf(a2, w[cq].x, acc[2][cq].x);
            acc[2][cq].y = fmaf(a2, w[cq].y, acc[2][cq].y);
            acc[2][cq].z = fmaf(a2, w[cq].z, acc[2][cq].z);
            acc[2][cq].w = fmaf(a2, w[cq].w, acc[2][cq].w);
        }
    }

    // Epilogue: optional tanh, store to out column slice
    #pragma unroll
    for (int r = 0; r < 3; r++) {
        int row = row0 + lr0 + r;
        if (row >= N_NODES) continue;
        #pragma unroll
        for (int cq = 0; cq < 4; cq++) {
            float4 v = acc[r][cq];
            if (TANH_AND_ZERO) {
                v.x = tanhf(v.x); v.y = tanhf(v.y);
                v.z = tanhf(v.z); v.w = tanhf(v.w);
            }
            out4[row * OUT_C4 + col_off4 + cg * 4 + cq] = v;
        }
    }
}

// ---------------------------------------------------------------------------
// Launch
// ---------------------------------------------------------------------------
extern "C" void kernel_launch(void* const* d_in, const int* in_sizes, int n_in,
                              void* d_out, int out_size) {
    const float* h   = (const float*)d_in[0];  // [50000, 64]
    const float* ew  = (const float*)d_in[1];  // [1250000]
    const float* Ws  = (const float*)d_in[2];  // [3, 64, 64]
    const float* bs  = (const float*)d_in[3];  // [3, 64]
    const int*   src = (const int*)d_in[4];    // [1250000]
    const int*   dst = (const int*)d_in[5];    // [1250000]
    float*       out = (float*)d_out;          // [50000, 256]

    float* gagg;
    cudaGetSymbolAddress((void**)&gagg, g_agg);

    const int THREADS = 256;

    // init: copy h into out[:,0:64) + zero agg
    {
        int total = N_NODES * D4;
        init_kernel<<<(total + THREADS - 1) / THREADS, THREADS>>>(
            (const float4*)h, (float4*)out, (float4*)gagg);
    }

    int scat_total   = N_EDGES * D4;
    int scat_blocks  = (scat_total + THREADS - 1) / THREADS;
    int xform_blocks = (N_NODES + TRB - 1) / TRB;   // 521

    for (int layer = 0; layer < L; layer++) {
        const float* W = Ws + layer * D * D;
        const float* b = bs + layer * D;
        int in_off4    = layer * D4;        // read slice
        int out_off4   = (layer + 1) * D4;  // write slice

        scatter_kernel<<<scat_blocks, THREADS>>>(
            (const float4*)out, in_off4, ew, src, dst, (float4*)gagg);

        if (layer < L - 1) {
            transform_kernel<true><<<xform_blocks, 128>>>(
                (float4*)gagg, (const float4*)W, b, (float4*)out, out_off4);
        } else {
            transform_kernel<false><<<xform_blocks, 128>>>(
                (float4*)gagg, (const float4*)W, b, (float4*)out, out_off4);
        }
    }
}

// round 9
// speedup vs baseline: 1.0075x; 1.0066x over previous
#include <cuda_runtime.h>

// Problem constants (fixed by the reference)
#define N_NODES 50000
#define N_EDGES 1250000
#define D 64
#define D4 16                 // float4 per feature row
#define L 3
#define OUT_C4 64             // 256 output cols / 4

// Scratch (allocation-free rule: __device__ global)
__device__ float g_agg[N_NODES * D];

// ---------------------------------------------------------------------------
// init: out[:, 0:64) = h  AND  agg = 0   (fused)
// ---------------------------------------------------------------------------
__global__ void init_kernel(const float4* __restrict__ h4,
                            float4* __restrict__ out4,
                            float4* __restrict__ agg4) {
    int idx = blockIdx.x * blockDim.x + threadIdx.x;
    if (idx >= N_NODES * D4) return;
    int row = idx >> 4;
    int c   = idx & 15;
    out4[row * OUT_C4 + c] = h4[idx];
    agg4[idx] = make_float4(0.f, 0.f, 0.f, 0.f);
}

// ---------------------------------------------------------------------------
// Edge-parallel gather-scale-scatter. Features are read from the out buffer
// (column slice of width 64 at col_off4), agg[dst] += feat[src] * w.
// One thread per (edge, float4-chunk); 16 chunks per edge.
// ---------------------------------------------------------------------------
__global__ void scatter_kernel(const float4* __restrict__ out4,
                               int col_off4,
                               const float*  __restrict__ ew,
                               const int*    __restrict__ src,
                               const int*    __restrict__ dst,
                               float4*       __restrict__ agg4) {
    int idx = blockIdx.x * blockDim.x + threadIdx.x;
    if (idx >= N_EDGES * D4) return;
    int e = idx >> 4;
    int c = idx & 15;

    int   s = src[e];
    int   d = dst[e];
    float w = ew[e];

    float4 v = out4[s * OUT_C4 + col_off4 + c];
    v.x *= w; v.y *= w; v.z *= w; v.w *= w;

#if defined(__CUDA_ARCH__) && (__CUDA_ARCH__ >= 900)
    atomicAdd(&agg4[d * D4 + c], v);   // RED.E.ADD.128
#else
    float* p = (float*)&agg4[d * D4 + c];
    atomicAdd(p + 0, v.x); atomicAdd(p + 1, v.y);
    atomicAdd(p + 2, v.z); atomicAdd(p + 3, v.w);
#endif
}

// ---------------------------------------------------------------------------
// Register-blocked transform:  y = agg @ W + b  (optional tanh)
//   - Block = 128 threads = 32 strips x 4 col-groups; strip owns 3 rows.
//   - Block covers 96 rows.  Thread computes a 3-row x 16-col register tile.
//   - W held in smem in a bank-permuted float4 layout (conflict-free reads).
//   - agg rows held in smem with stride-65 padding (conflict-free scalar reads).
//   - After loading agg into smem, agg is zeroed (ready for next scatter).
// Writes result into out[:, col_off4*4 : +64).
// ---------------------------------------------------------------------------
#define TRB 96   // rows per block

template <bool TANH_AND_ZERO>
__global__ void __launch_bounds__(128) transform_kernel(
        float4* __restrict__ agg4,
        const float4* __restrict__ W4,   // [1024] float4 = [64,64] row-major
        const float*  __restrict__ b,    // [64]
        float4* __restrict__ out4,       // [N, 64] float4
        int col_off4) {
    __shared__ float4 sW[1024];          // 16 KB, permuted: sW[(cq*64+k)*4+cg]
    __shared__ float  sA[TRB * 65];      // ~25 KB, padded rows
    __shared__ float  sb[D];

    int tid = threadIdx.x;

    // Load W into permuted smem layout.
    // Global chunk i = k*16 + (cg*4 + cq)  ->  sW[(cq*64 + k)*4 + cg]
    for (int i = tid; i < 1024; i += 128) {
        int k  = i >> 4;
        int ch = i & 15;
        int cg = ch >> 2;
        int cq = ch & 3;
        sW[(cq * 64 + k) * 4 + cg] = W4[i];
    }
    if (tid < D) sb[tid] = b[tid];

    // Load agg rows into smem (padded) and zero agg in gmem.
    int row0  = blockIdx.x * TRB;
    int base4 = row0 * D4;
    const float4 z4 = make_float4(0.f, 0.f, 0.f, 0.f);
    for (int i = tid; i < TRB * D4; i += 128) {
        float4 v = z4;
        int g = base4 + i;
        if (g < N_NODES * D4) {
            v = agg4[g];
            if (TANH_AND_ZERO) agg4[g] = z4;
        }
        int lr = i >> 4;
        int c4 = i & 15;
        float* p = &sA[lr * 65 + c4 * 4];
        p[0] = v.x; p[1] = v.y; p[2] = v.z; p[3] = v.w;
    }
    __syncthreads();

    int cg    = tid & 3;        // col group: cols [cg*16, cg*16+16)
    int strip = tid >> 2;       // 0..31
    int lr0   = strip * 3;      // 3 rows per strip; strips 0..31 -> rows 0..95

    // Init accumulators with bias
    float4 acc[3][4];
    #pragma unroll
    for (int r = 0; r < 3; r++)
        #pragma unroll
        for (int cq = 0; cq < 4; cq++) {
            int c = cg * 16 + cq * 4;
            acc[r][cq] = make_float4(sb[c], sb[c + 1], sb[c + 2], sb[c + 3]);
        }

    // Main loop over k
    #pragma unroll 4
    for (int k = 0; k < D; k++) {
        float a0 = sA[(lr0 + 0) * 65 + k];
        float a1 = sA[(lr0 + 1) * 65 + k];
        float a2 = sA[(lr0 + 2) * 65 + k];
        float4 w[4];
        #pragma unroll
        for (int cq = 0; cq < 4; cq++)
            w[cq] = sW[(cq * 64 + k) * 4 + cg];

        #pragma unroll
        for (int cq = 0; cq < 4; cq++) {
            acc[0][cq].x = fmaf(a0, w[cq].x, acc[0][cq].x);
            acc[0][cq].y = fmaf(a0, w[cq].y, acc[0][cq].y);
            acc[0][cq].z = fmaf(a0, w[cq].z, acc[0][cq].z);
            acc[0][cq].w = fmaf(a0, w[cq].w, acc[0][cq].w);
            acc[1][cq].x = fmaf(a1, w[cq].x, acc[1][cq].x);
            acc[1][cq].y = fmaf(a1, w[cq].y, acc[1][cq].y);
            acc[1][cq].z = fmaf(a1, w[cq].z, acc[1][cq].z);
            acc[1][cq].w = fmaf(a1, w[cq].w, acc[1][cq].w);
            acc[2][cq].x = fmaf(a2, w[cq].x, acc[2][cq].x);
            acc[2][cq].y = fmaf(a2, w[cq].y, acc[2][cq].y);
            acc[2][cq].z = fmaf(a2, w[cq].z, acc[2][cq].z);
            acc[2][cq].w = fmaf(a2, w[cq].w, acc[2][cq].w);
        }
    }

    // Epilogue: optional tanh, store to out column slice
    #pragma unroll
    for (int r = 0; r < 3; r++) {
        int row = row0 + lr0 + r;
        if (row >= N_NODES) continue;
        #pragma unroll
        for (int cq = 0; cq < 4; cq++) {
            float4 v = acc[r][cq];
            if (TANH_AND_ZERO) {
                v.x = tanhf(v.x); v.y = tanhf(v.y);
                v.z = tanhf(v.z); v.w = tanhf(v.w);
            }
            out4[row * OUT_C4 + col_off4 + cg * 4 + cq] = v;
        }
    }
}

// ---------------------------------------------------------------------------
// Launch
// ---------------------------------------------------------------------------
extern "C" void kernel_launch(void* const* d_in, const int* in_sizes, int n_in,
                              void* d_out, int out_size) {
    const float* h   = (const float*)d_in[0];  // [50000, 64]
    const float* ew  = (const float*)d_in[1];  // [1250000]
    const float* Ws  = (const float*)d_in[2];  // [3, 64, 64]
    const float* bs  = (const float*)d_in[3];  // [3, 64]
    const int*   src = (const int*)d_in[4];    // [1250000]
    const int*   dst = (const int*)d_in[5];    // [1250000]
    float*       out = (float*)d_out;          // [50000, 256]

    float* gagg;
    cudaGetSymbolAddress((void**)&gagg, g_agg);

    const int THREADS = 256;

    // init: copy h into out[:,0:64) + zero agg
    {
        int total = N_NODES * D4;
        init_kernel<<<(total + THREADS - 1) / THREADS, THREADS>>>(
            (const float4*)h, (float4*)out, (float4*)gagg);
    }

    int scat_total   = N_EDGES * D4;
    int scat_blocks  = (scat_total + THREADS - 1) / THREADS;
    int xform_blocks = (N_NODES + TRB - 1) / TRB;   // 521

    for (int layer = 0; layer < L; layer++) {
        const float* W = Ws + layer * D * D;
        const float* b = bs + layer * D;
        int in_off4    = layer * D4;        // read slice
        int out_off4   = (layer + 1) * D4;  // write slice

        scatter_kernel<<<scat_blocks, THREADS>>>(
            (const float4*)out, in_off4, ew, src, dst, (float4*)gagg);

        if (layer < L - 1) {
            transform_kernel<true><<<xform_blocks, 128>>>(
                (float4*)gagg, (const float4*)W, b, (float4*)out, out_off4);
        } else {
            transform_kernel<false><<<xform_blocks, 128>>>(
                (float4*)gagg, (const float4*)W, b, (float4*)out, out_off4);
        }
    }
}